// round 1
// baseline (speedup 1.0000x reference)
#include <cuda_runtime.h>
#include <math.h>

#define PP 4
#define BB 128
#define DD 512
#define NN 32768
#define KK 10
#define TEMP_INV 2.0f
#define SCALEC 10.0f
#define KL_WEIGHT (59.0f/120.0f)

// ---------------- scratch (no allocations allowed) ----------------
__device__ float g_img[PP*BB*DD];     // normalized feature
__device__ float g_txt[PP*BB*DD];     // normalized transposed text feature
__device__ float g_fn2[PP*BB];        // ||feature||^2
__device__ float g_negmask[NN];       // 1.0 keep / 0.0 masked
__device__ float g_negsum[PP*BB];     // sum_n exp(-10*dist)*mask
__device__ float g_lp[PP];            // per-p sum_b (y-x)
__device__ float g_klp[PP];           // per-p sum_b (kl1+kl2)

// ---------------- init: mask=1, zero accumulators ----------------
__global__ void k_init() {
    int i = blockIdx.x * blockDim.x + threadIdx.x;
    if (i < NN) g_negmask[i] = 1.0f;
    if (i < PP*BB) g_negsum[i] = 0.0f;
    if (i < PP) { g_lp[i] = 0.0f; g_klp[i] = 0.0f; }
}

// ---------------- scatter zeros into mask ----------------
__global__ void k_scatter(const int* __restrict__ cross, const int* __restrict__ pos) {
    int i = blockIdx.x * blockDim.x + threadIdx.x;
    if (i < BB*KK) g_negmask[cross[i]] = 0.0f;
    else if (i < BB*KK + BB) g_negmask[pos[i - BB*KK]] = 0.0f;
}

// ---------------- normalize rows + fn2 ----------------
__global__ void __launch_bounds__(128) k_prep(const float* __restrict__ feature,
                                              const float* __restrict__ text) {
    __shared__ float s4[4];
    int pb = blockIdx.x;            // p*128 + b
    int p = pb >> 7, b = pb & 127;
    int tid = threadIdx.x;          // 128 threads, 4 floats each

    // feature[p][b]
    float4 f = ((const float4*)(feature + (size_t)pb * DD))[tid];
    float ss = f.x*f.x + f.y*f.y + f.z*f.z + f.w*f.w;
    #pragma unroll
    for (int o = 16; o; o >>= 1) ss += __shfl_xor_sync(~0u, ss, o);
    if ((tid & 31) == 0) s4[tid >> 5] = ss;
    __syncthreads();
    ss = s4[0] + s4[1] + s4[2] + s4[3];
    if (tid == 0) g_fn2[pb] = ss;
    float inv = 1.0f / fmaxf(sqrtf(ss), 1e-12f);
    ((float4*)(g_img + (size_t)pb * DD))[tid] =
        make_float4(f.x*inv, f.y*inv, f.z*inv, f.w*inv);
    __syncthreads();

    // text[b][p] -> g_txt[p][b]
    float4 t = ((const float4*)(text + ((size_t)b * PP + p) * DD))[tid];
    float ts = t.x*t.x + t.y*t.y + t.z*t.z + t.w*t.w;
    #pragma unroll
    for (int o = 16; o; o >>= 1) ts += __shfl_xor_sync(~0u, ts, o);
    if ((tid & 31) == 0) s4[tid >> 5] = ts;
    __syncthreads();
    ts = s4[0] + s4[1] + s4[2] + s4[3];
    float tinv = 1.0f / fmaxf(sqrtf(ts), 1e-12f);
    ((float4*)(g_txt + (size_t)pb * DD))[tid] =
        make_float4(t.x*tinv, t.y*tinv, t.z*tinv, t.w*tinv);
}

// ---------------- neg-term fused SGEMM ----------------
// grid (N/64, P), 256 threads. Block: 128 b x 64 n tile over full K=512.
// Epilogue fuses dist/exp/mask and reduces into g_negsum[p][b].
#define BN 64
#define KC 32
__global__ void __launch_bounds__(256) k_neg(const float* __restrict__ feature,
                                             const float* __restrict__ centers) {
    __shared__ float As[KC][132];   // [k][b], padded
    __shared__ float Bs[KC][68];    // [k][n], padded
    __shared__ float s_cn2[BN];
    __shared__ float s_bsum[BB];
    int p  = blockIdx.y;
    int n0 = blockIdx.x * BN;
    int tid = threadIdx.x;
    int tx = tid & 15, ty = tid >> 4;   // tx -> n (4 each), ty -> b (8 each)

    const float* A  = feature + (size_t)p * BB * DD;
    const float* Bp = centers + ((size_t)p * NN + n0) * DD;

    float acc[8][4];
    #pragma unroll
    for (int i = 0; i < 8; i++)
        #pragma unroll
        for (int j = 0; j < 4; j++) acc[i][j] = 0.0f;
    float cn2 = 0.0f;

    for (int k0 = 0; k0 < DD; k0 += KC) {
        #pragma unroll
        for (int i = 0; i < 4; i++) {           // A tile: 128x32
            int idx = tid + i * 256;
            int row = idx >> 3, c4 = (idx & 7) << 2;
            float4 v = *(const float4*)(A + (size_t)row * DD + k0 + c4);
            As[c4][row] = v.x; As[c4+1][row] = v.y; As[c4+2][row] = v.z; As[c4+3][row] = v.w;
        }
        #pragma unroll
        for (int i = 0; i < 2; i++) {           // B tile: 64x32
            int idx = tid + i * 256;
            int row = idx >> 3, c4 = (idx & 7) << 2;
            float4 v = *(const float4*)(Bp + (size_t)row * DD + k0 + c4);
            Bs[c4][row] = v.x; Bs[c4+1][row] = v.y; Bs[c4+2][row] = v.z; Bs[c4+3][row] = v.w;
        }
        __syncthreads();
        if (tid < BN) {                         // center norms from smem tile
            #pragma unroll
            for (int kk = 0; kk < KC; kk++) { float v = Bs[kk][tid]; cn2 += v * v; }
        }
        #pragma unroll
        for (int kk = 0; kk < KC; kk++) {
            float4 a0 = *(const float4*)&As[kk][ty*8];
            float4 a1 = *(const float4*)&As[kk][ty*8+4];
            float4 bq = *(const float4*)&Bs[kk][tx*4];
            float a[8] = {a0.x,a0.y,a0.z,a0.w,a1.x,a1.y,a1.z,a1.w};
            float bv[4] = {bq.x,bq.y,bq.z,bq.w};
            #pragma unroll
            for (int i = 0; i < 8; i++)
                #pragma unroll
                for (int j = 0; j < 4; j++)
                    acc[i][j] += a[i] * bv[j];
        }
        __syncthreads();
    }

    if (tid < BN) s_cn2[tid] = cn2;
    if (tid < BB) s_bsum[tid] = 0.0f;
    __syncthreads();

    float m[4];
    #pragma unroll
    for (int j = 0; j < 4; j++) m[j] = g_negmask[n0 + tx*4 + j];

    #pragma unroll
    for (int i = 0; i < 8; i++) {
        int b = ty * 8 + i;
        float fn2 = g_fn2[p * BB + b];
        float s = 0.0f;
        #pragma unroll
        for (int j = 0; j < 4; j++) {
            float pd2  = fn2 + s_cn2[tx*4+j] - 2.0f * acc[i][j];
            float dist = sqrtf(fmaxf(pd2, 1e-12f));
            s += __expf(-SCALEC * dist) * m[j];
        }
        atomicAdd(&s_bsum[b], s);
    }
    __syncthreads();
    if (tid < BB) atomicAdd(&g_negsum[p * BB + tid], s_bsum[tid]);
}

// ---------------- positive term + per-p (y - x) ----------------
__global__ void __launch_bounds__(128) k_pos(const float* __restrict__ feature,
                                             const float* __restrict__ centers,
                                             const int* __restrict__ cross) {
    __shared__ float s_f[DD];
    __shared__ float s_e[KK];
    int pb = blockIdx.x; int p = pb >> 7, b = pb & 127;
    int tid = threadIdx.x;
    ((float4*)s_f)[tid] = ((const float4*)(feature + (size_t)pb * DD))[tid];
    __syncthreads();
    int w = tid >> 5, lane = tid & 31;
    float fn2 = g_fn2[pb];
    for (int k = w; k < KK; k += 4) {
        int n = cross[b * KK + k];
        const float4* c4 = (const float4*)(centers + ((size_t)p * NN + n) * DD);
        float dot = 0.0f, cn2 = 0.0f;
        for (int i = lane; i < DD/4; i += 32) {
            float4 c = c4[i];
            float4 f = ((const float4*)s_f)[i];
            dot += f.x*c.x + f.y*c.y + f.z*c.z + f.w*c.w;
            cn2 += c.x*c.x + c.y*c.y + c.z*c.z + c.w*c.w;
        }
        #pragma unroll
        for (int o = 16; o; o >>= 1) {
            dot += __shfl_xor_sync(~0u, dot, o);
            cn2 += __shfl_xor_sync(~0u, cn2, o);
        }
        if (lane == 0) {
            float dist = sqrtf(fmaxf(fn2 + cn2 - 2.0f * dot, 1e-12f));
            s_e[k] = expf(-SCALEC * dist);
        }
    }
    __syncthreads();
    if (tid == 0) {
        float se = 0.0f;
        for (int k = 0; k < KK; k++) se += s_e[k];
        float x = logf(se);
        float y = logf(g_negsum[pb]);
        atomicAdd(&g_lp[p], y - x);
    }
}

// ---------------- align loss ----------------
// One block per (p,b): thread c computes sim row entries; colm/valid are
// provably all-true (diagonal cos/TEMP = 2 > 0.7), so plain log_softmax + KL.
__global__ void __launch_bounds__(128) k_align() {
    __shared__ float tile[128][65];
    __shared__ float s_red[4];
    int pb = blockIdx.x; int p = pb >> 7, b = pb & 127;
    int tid = threadIdx.x;

    float simg = 0.0f, stxt = 0.0f;
    for (int pass = 0; pass < 2; pass++) {
        const float* src = pass == 0 ? g_img : g_txt;
        float accd = 0.0f;
        for (int c0 = 0; c0 < DD; c0 += 64) {
            #pragma unroll
            for (int i = 0; i < 16; i++) {
                int idx = tid + i * 128;        // 2048 float4 slots
                int row = idx >> 4, f4 = (idx & 15) << 2;
                float4 v = *(const float4*)(src + ((size_t)p * BB + row) * DD + c0 + f4);
                tile[row][f4] = v.x; tile[row][f4+1] = v.y;
                tile[row][f4+2] = v.z; tile[row][f4+3] = v.w;
            }
            __syncthreads();
            #pragma unroll
            for (int d = 0; d < 64; d++) accd += tile[b][d] * tile[tid][d];
            __syncthreads();
        }
        if (pass == 0) simg = accd; else stxt = accd;
    }

    float li = simg * TEMP_INV;
    float lt = stxt * TEMP_INV;

    // log_softmax over c for img
    float v = li;
    #pragma unroll
    for (int o = 16; o; o >>= 1) v = fmaxf(v, __shfl_xor_sync(~0u, v, o));
    if ((tid & 31) == 0) s_red[tid >> 5] = v;
    __syncthreads();
    float mi = fmaxf(fmaxf(s_red[0], s_red[1]), fmaxf(s_red[2], s_red[3]));
    __syncthreads();
    v = expf(li - mi);
    #pragma unroll
    for (int o = 16; o; o >>= 1) v += __shfl_xor_sync(~0u, v, o);
    if ((tid & 31) == 0) s_red[tid >> 5] = v;
    __syncthreads();
    float si = s_red[0] + s_red[1] + s_red[2] + s_red[3];
    __syncthreads();
    float lpi = li - mi - logf(si);

    // log_softmax over c for txt
    v = lt;
    #pragma unroll
    for (int o = 16; o; o >>= 1) v = fmaxf(v, __shfl_xor_sync(~0u, v, o));
    if ((tid & 31) == 0) s_red[tid >> 5] = v;
    __syncthreads();
    float mt = fmaxf(fmaxf(s_red[0], s_red[1]), fmaxf(s_red[2], s_red[3]));
    __syncthreads();
    v = expf(lt - mt);
    #pragma unroll
    for (int o = 16; o; o >>= 1) v += __shfl_xor_sync(~0u, v, o);
    if ((tid & 31) == 0) s_red[tid >> 5] = v;
    __syncthreads();
    float st = s_red[0] + s_red[1] + s_red[2] + s_red[3];
    __syncthreads();
    float lpt = lt - mt - logf(st);

    // kl1 + kl2 contribution of this (b, c=tid)
    float kl = expf(lpt) * (lpt - lpi) + expf(lpi) * (lpi - lpt);
    #pragma unroll
    for (int o = 16; o; o >>= 1) kl += __shfl_xor_sync(~0u, kl, o);
    if ((tid & 31) == 0) s_red[tid >> 5] = kl;
    __syncthreads();
    if (tid == 0) {
        float kls = s_red[0] + s_red[1] + s_red[2] + s_red[3];
        atomicAdd(&g_klp[p], kls);
    }
}

// ---------------- finalize + pos_vid gather ----------------
__global__ void k_final(const int* __restrict__ cross, const int* __restrict__ vid,
                        float* __restrict__ out) {
    int i = blockIdx.x * blockDim.x + threadIdx.x;
    if (i < BB*KK) out[3 + i] = (float)vid[cross[i]];
    if (i == 0) {
        float contr = 0.0f;
        for (int p = 0; p < PP; p++) {
            float lp = g_lp[p] / (float)BB;
            if (isnan(lp)) lp = 0.0f;
            contr += lp;
        }
        contr /= (float)PP;
        float align = 0.0f;
        for (int p = 0; p < PP; p++) align += 0.5f * g_klp[p] / (float)BB;
        out[0] = contr + KL_WEIGHT * align;
        out[1] = contr;
        out[2] = align;
    }
}

// ---------------- launch ----------------
extern "C" void kernel_launch(void* const* d_in, const int* in_sizes, int n_in,
                              void* d_out, int out_size) {
    const float* feature = (const float*)d_in[0];  // (P,B,D)
    const float* text    = (const float*)d_in[1];  // (B,P,D)
    const float* centers = (const float*)d_in[2];  // (P,N,D)
    const int*   positn  = (const int*)d_in[3];    // (B,)
    const int*   cross   = (const int*)d_in[4];    // (B,K)
    const int*   vid     = (const int*)d_in[5];    // (N,)
    float* out = (float*)d_out;

    k_init<<<128, 256>>>();
    k_scatter<<<6, 256>>>(cross, positn);
    k_prep<<<PP*BB, 128>>>(feature, text);
    k_neg<<<dim3(NN/BN, PP), 256>>>(feature, centers);
    k_pos<<<PP*BB, 128>>>(feature, centers, cross);
    k_align<<<PP*BB, 128>>>();
    k_final<<<6, 256>>>(cross, vid, out);
}

// round 4
// speedup vs baseline: 2.3899x; 2.3899x over previous
#include <cuda_runtime.h>
#include <cstdint>
#include <math.h>

#define PP 4
#define BB 128
#define DD 512
#define NN 32768
#define KK 10
#define TEMP_INV 2.0f
#define SCALEC 10.0f
#define KL_WEIGHT (59.0f/120.0f)

// ================= scratch =================
__device__ float g_img[PP*BB*DD];
__device__ float g_txt[PP*BB*DD];
__device__ float g_fn2[PP*BB];
__device__ float g_negmask[NN];
__device__ float g_negsum[PP*BB];
__device__ float g_lp[PP];
__device__ float g_klp[PP];

// ================= helpers =================
__device__ __forceinline__ void cp16(uint32_t dst, const void* src) {
    asm volatile("cp.async.cg.shared.global [%0], [%1], 16;" :: "r"(dst), "l"(src));
}
#define CP_COMMIT() asm volatile("cp.async.commit_group;" ::: "memory")
#define CP_WAIT1()  asm volatile("cp.async.wait_group 1;" ::: "memory")
#define CP_WAIT0()  asm volatile("cp.async.wait_group 0;" ::: "memory")

__device__ __forceinline__ uint32_t smem_u32(const void* p) {
    uint32_t a;
    asm("{ .reg .u64 t; cvta.to.shared.u64 t, %1; cvt.u32.u64 %0, t; }" : "=r"(a) : "l"(p));
    return a;
}

__device__ __forceinline__ void mma_tf32(float* d, const uint32_t* a, const uint32_t* b) {
    asm volatile(
        "mma.sync.aligned.m16n8k8.row.col.f32.tf32.tf32.f32 "
        "{%0,%1,%2,%3}, {%4,%5,%6,%7}, {%8,%9}, {%0,%1,%2,%3};"
        : "+f"(d[0]), "+f"(d[1]), "+f"(d[2]), "+f"(d[3])
        : "r"(a[0]), "r"(a[1]), "r"(a[2]), "r"(a[3]), "r"(b[0]), "r"(b[1]));
}

// ================= init / scatter =================
__global__ void k_init() {
    int i = blockIdx.x * blockDim.x + threadIdx.x;
    if (i < NN) g_negmask[i] = 1.0f;
    if (i < PP*BB) g_negsum[i] = 0.0f;
    if (i < PP) { g_lp[i] = 0.0f; g_klp[i] = 0.0f; }
}
__global__ void k_scatter(const int* __restrict__ cross, const int* __restrict__ pos) {
    int i = blockIdx.x * blockDim.x + threadIdx.x;
    if (i < BB*KK) g_negmask[cross[i]] = 0.0f;
    else if (i < BB*KK + BB) g_negmask[pos[i - BB*KK]] = 0.0f;
}

// ================= normalize + fn2 =================
__global__ void __launch_bounds__(128) k_prep(const float* __restrict__ feature,
                                              const float* __restrict__ text) {
    __shared__ float s4[4];
    int pb = blockIdx.x;
    int p = pb >> 7, b = pb & 127;
    int tid = threadIdx.x;

    float4 f = ((const float4*)(feature + (size_t)pb * DD))[tid];
    float ss = f.x*f.x + f.y*f.y + f.z*f.z + f.w*f.w;
    #pragma unroll
    for (int o = 16; o; o >>= 1) ss += __shfl_xor_sync(~0u, ss, o);
    if ((tid & 31) == 0) s4[tid >> 5] = ss;
    __syncthreads();
    ss = s4[0] + s4[1] + s4[2] + s4[3];
    if (tid == 0) g_fn2[pb] = ss;
    float inv = 1.0f / fmaxf(sqrtf(ss), 1e-12f);
    ((float4*)(g_img + (size_t)pb * DD))[tid] =
        make_float4(f.x*inv, f.y*inv, f.z*inv, f.w*inv);
    __syncthreads();

    float4 t = ((const float4*)(text + ((size_t)b * PP + p) * DD))[tid];
    float ts = t.x*t.x + t.y*t.y + t.z*t.z + t.w*t.w;
    #pragma unroll
    for (int o = 16; o; o >>= 1) ts += __shfl_xor_sync(~0u, ts, o);
    if ((tid & 31) == 0) s4[tid >> 5] = ts;
    __syncthreads();
    ts = s4[0] + s4[1] + s4[2] + s4[3];
    float tinv = 1.0f / fmaxf(sqrtf(ts), 1e-12f);
    ((float4*)(g_txt + (size_t)pb * DD))[tid] =
        make_float4(t.x*tinv, t.y*tinv, t.z*tinv, t.w*tinv);
}

// ================= neg term: tf32 mma.sync GEMM =================
// Block (n0 = bx*128, p = by): D[128 b][128 n] = feature[p] . centers[p, n0:+128]^T
// 8 warps, warp tile 64x32 via m16n8k8. K=512 in 16 chunks of 32.
// cp.async double buffer; cn2 computed from the smem B tile.
#define KC 32
#define PITCH 36                  // floats; (4*row + k) mod 32 distinct -> conflict-free frags
#define TILE_BYTES (128 * PITCH * 4)      // 18432 B per matrix per stage
#define STAGE_BYTES (2 * TILE_BYTES)      // A + B
#define NEG_SMEM (2 * STAGE_BYTES)        // double buffer = 73728 B

__device__ __forceinline__ void load_chunk(const float* __restrict__ A,
                                           const float* __restrict__ B,
                                           uint32_t base, int c, int stage, int tid) {
    int k0 = c * KC;
    uint32_t sA = base + (uint32_t)stage * STAGE_BYTES;
    uint32_t sB = sA + TILE_BYTES;
    #pragma unroll
    for (int i = 0; i < 8; i++) {
        int q = i * 256 + tid;
        int row = (q >> 3) & 127;
        int g = q & 7;
        uint32_t off = (uint32_t)(row * 144 + g * 16);   // PITCH*4 = 144 B rows
        if (q < 1024) cp16(sA + off, A + (size_t)row * DD + k0 + g * 4);
        else          cp16(sB + off, B + (size_t)row * DD + k0 + g * 4);
    }
    CP_COMMIT();
}

__global__ void __launch_bounds__(256, 2)
k_neg(const float* __restrict__ feature, const float* __restrict__ centers) {
    extern __shared__ __align__(16) char dsm[];
    __shared__ float s_cn2[128];
    __shared__ float s_fn2[128];
    __shared__ float s_mask[128];
    __shared__ float s_bsum[128];

    uint32_t base = smem_u32(dsm);
    int tid = threadIdx.x;
    int wid = tid >> 5, lane = tid & 31;
    int row4 = lane >> 2, col4 = lane & 3;
    int warp_m = wid >> 2, warp_n = wid & 3;   // 2 x 4 warps
    int mbase = warp_m * 64, nbase = warp_n * 32;
    int p = blockIdx.y;
    int n0 = blockIdx.x * 128;

    if (tid < 128) {
        s_mask[tid] = g_negmask[n0 + tid];
        s_fn2[tid] = g_fn2[p * BB + tid];
        s_bsum[tid] = 0.0f;
    }

    const float* A = feature + (size_t)p * BB * DD;
    const float* B = centers + ((size_t)p * NN + n0) * DD;

    float acc[4][4][4];
    #pragma unroll
    for (int i = 0; i < 4; i++)
        #pragma unroll
        for (int j = 0; j < 4; j++)
            #pragma unroll
            for (int r = 0; r < 4; r++) acc[i][j][r] = 0.0f;
    float cn2acc = 0.0f;

    load_chunk(A, B, base, 0, 0, tid);

    for (int c = 0; c < 16; c++) {
        int stage = c & 1;
        if (c + 1 < 16) {
            load_chunk(A, B, base, c + 1, (c + 1) & 1, tid);
            CP_WAIT1();
        } else {
            CP_WAIT0();
        }
        __syncthreads();

        const float* sA = (const float*)(dsm + (size_t)stage * STAGE_BYTES);
        const float* sB = (const float*)(dsm + (size_t)stage * STAGE_BYTES + TILE_BYTES);

        // cn2 partial: row tid of the B chunk
        if (tid < 128) {
            const float4* r4 = (const float4*)(sB + tid * PITCH);
            #pragma unroll
            for (int g = 0; g < 8; g++) {
                float4 v = r4[g];
                cn2acc += v.x*v.x + v.y*v.y + v.z*v.z + v.w*v.w;
            }
        }

        #pragma unroll
        for (int kk = 0; kk < 4; kk++) {
            int kf = kk * 8;
            uint32_t afr[4][4];
            #pragma unroll
            for (int i = 0; i < 4; i++) {
                const float* Ar = sA + (mbase + i * 16 + row4) * PITCH + kf + col4;
                afr[i][0] = __float_as_uint(Ar[0]);
                afr[i][1] = __float_as_uint(Ar[8 * PITCH]);
                afr[i][2] = __float_as_uint(Ar[4]);
                afr[i][3] = __float_as_uint(Ar[8 * PITCH + 4]);
            }
            uint32_t bfr[4][2];
            #pragma unroll
            for (int j = 0; j < 4; j++) {
                const float* Br = sB + (nbase + j * 8 + row4) * PITCH + kf + col4;
                bfr[j][0] = __float_as_uint(Br[0]);
                bfr[j][1] = __float_as_uint(Br[4]);
            }
            #pragma unroll
            for (int i = 0; i < 4; i++)
                #pragma unroll
                for (int j = 0; j < 4; j++)
                    mma_tf32(acc[i][j], afr[i], bfr[j]);
        }
        __syncthreads();    // readers done before next chunk overwrites this stage
    }

    if (tid < 128) s_cn2[tid] = cn2acc;
    __syncthreads();

    // Epilogue: pd2 -> dist -> exp -> masked sum per b
    #pragma unroll
    for (int i = 0; i < 4; i++) {
        #pragma unroll
        for (int half = 0; half < 2; half++) {
            int b = mbase + i * 16 + row4 + half * 8;
            float fn2v = s_fn2[b];
            float s = 0.0f;
            #pragma unroll
            for (int j = 0; j < 4; j++) {
                #pragma unroll
                for (int q = 0; q < 2; q++) {
                    int n = nbase + j * 8 + col4 * 2 + q;
                    float v = acc[i][j][half * 2 + q];
                    float pd2 = fn2v + s_cn2[n] - 2.0f * v;
                    float dist = sqrtf(fmaxf(pd2, 1e-12f));
                    s += __expf(-SCALEC * dist) * s_mask[n];
                }
            }
            atomicAdd(&s_bsum[b], s);
        }
    }
    __syncthreads();
    if (tid < 128) atomicAdd(&g_negsum[p * BB + tid], s_bsum[tid]);
}

// ================= positive term =================
__global__ void __launch_bounds__(128) k_pos(const float* __restrict__ feature,
                                             const float* __restrict__ centers,
                                             const int* __restrict__ cross) {
    __shared__ float s_f[DD];
    __shared__ float s_e[KK];
    int pb = blockIdx.x; int p = pb >> 7, b = pb & 127;
    int tid = threadIdx.x;
    ((float4*)s_f)[tid] = ((const float4*)(feature + (size_t)pb * DD))[tid];
    __syncthreads();
    int w = tid >> 5, lane = tid & 31;
    float fn2 = g_fn2[pb];
    for (int k = w; k < KK; k += 4) {
        int n = cross[b * KK + k];
        const float4* c4 = (const float4*)(centers + ((size_t)p * NN + n) * DD);
        float dot = 0.0f, cn2 = 0.0f;
        for (int i = lane; i < DD/4; i += 32) {
            float4 c = c4[i];
            float4 f = ((const float4*)s_f)[i];
            dot += f.x*c.x + f.y*c.y + f.z*c.z + f.w*c.w;
            cn2 += c.x*c.x + c.y*c.y + c.z*c.z + c.w*c.w;
        }
        #pragma unroll
        for (int o = 16; o; o >>= 1) {
            dot += __shfl_xor_sync(~0u, dot, o);
            cn2 += __shfl_xor_sync(~0u, cn2, o);
        }
        if (lane == 0) {
            float dist = sqrtf(fmaxf(fn2 + cn2 - 2.0f * dot, 1e-12f));
            s_e[k] = expf(-SCALEC * dist);
        }
    }
    __syncthreads();
    if (tid == 0) {
        float se = 0.0f;
        for (int k = 0; k < KK; k++) se += s_e[k];
        atomicAdd(&g_lp[p], logf(g_negsum[pb]) - logf(se));
    }
}

// ================= align loss =================
// grid (16, P): block owns 8 rows of the 128x128 sim matrices for both img & txt.
// colm/valid are provably all-true (diag cos/TEMP = 2 > 0.7).
__global__ void __launch_bounds__(256) k_align() {
    __shared__ float rows[8][512];
    __shared__ float chunk[128][36];
    __shared__ float sim[2][8][128];
    int p = blockIdx.y;
    int r0 = blockIdx.x * 8;
    int tid = threadIdx.x;
    int c = tid & 127, rh = tid >> 7;

    for (int src = 0; src < 2; src++) {
        const float* X = (src ? g_txt : g_img) + (size_t)p * BB * DD;
        __syncthreads();
        for (int i = tid; i < 8 * 128; i += 256) {
            int r = i >> 7, g = i & 127;
            ((float4*)rows[r])[g] = ((const float4*)(X + (size_t)(r0 + r) * DD))[g];
        }
        float acc[4] = {0.f, 0.f, 0.f, 0.f};
        for (int d0 = 0; d0 < 512; d0 += 32) {
            __syncthreads();
            for (int i = tid; i < 1024; i += 256) {
                int r = i >> 3, g = i & 7;
                float4 v = ((const float4*)(X + (size_t)r * DD + d0))[g];
                chunk[r][g*4+0] = v.x; chunk[r][g*4+1] = v.y;
                chunk[r][g*4+2] = v.z; chunk[r][g*4+3] = v.w;
            }
            __syncthreads();
            #pragma unroll
            for (int dg = 0; dg < 8; dg++) {
                float4 cv = *(const float4*)&chunk[c][dg * 4];
                #pragma unroll
                for (int i = 0; i < 4; i++) {
                    float4 rv = *(const float4*)&rows[rh * 4 + i][d0 + dg * 4];
                    acc[i] += rv.x*cv.x + rv.y*cv.y + rv.z*cv.z + rv.w*cv.w;
                }
            }
        }
        #pragma unroll
        for (int i = 0; i < 4; i++) sim[src][rh * 4 + i][c] = acc[i] * TEMP_INV;
    }
    __syncthreads();

    int w = tid >> 5, lane = tid & 31;
    float li[4], lt[4];
    #pragma unroll
    for (int j = 0; j < 4; j++) {
        li[j] = sim[0][w][lane + 32 * j];
        lt[j] = sim[1][w][lane + 32 * j];
    }
    float mi = fmaxf(fmaxf(li[0], li[1]), fmaxf(li[2], li[3]));
    float mt = fmaxf(fmaxf(lt[0], lt[1]), fmaxf(lt[2], lt[3]));
    #pragma unroll
    for (int o = 16; o; o >>= 1) {
        mi = fmaxf(mi, __shfl_xor_sync(~0u, mi, o));
        mt = fmaxf(mt, __shfl_xor_sync(~0u, mt, o));
    }
    float si = 0.f, st = 0.f;
    #pragma unroll
    for (int j = 0; j < 4; j++) { si += expf(li[j] - mi); st += expf(lt[j] - mt); }
    #pragma unroll
    for (int o = 16; o; o >>= 1) {
        si += __shfl_xor_sync(~0u, si, o);
        st += __shfl_xor_sync(~0u, st, o);
    }
    float Li = mi + logf(si), Lt = mt + logf(st);
    float kl = 0.f;
    #pragma unroll
    for (int j = 0; j < 4; j++) {
        float lpi = li[j] - Li, lpt = lt[j] - Lt;
        kl += expf(lpt) * (lpt - lpi) + expf(lpi) * (lpi - lpt);
    }
    #pragma unroll
    for (int o = 16; o; o >>= 1) kl += __shfl_xor_sync(~0u, kl, o);
    if (lane == 0) atomicAdd(&g_klp[p], kl);
}

// ================= finalize =================
__global__ void k_final(const int* __restrict__ cross, const int* __restrict__ vid,
                        float* __restrict__ out) {
    int i = blockIdx.x * blockDim.x + threadIdx.x;
    if (i < BB*KK) out[3 + i] = (float)vid[cross[i]];
    if (i == 0) {
        float contr = 0.0f;
        for (int p = 0; p < PP; p++) {
            float lp = g_lp[p] / (float)BB;
            if (isnan(lp)) lp = 0.0f;
            contr += lp;
        }
        contr /= (float)PP;
        float align = 0.0f;
        for (int p = 0; p < PP; p++) align += 0.5f * g_klp[p] / (float)BB;
        out[0] = contr + KL_WEIGHT * align;
        out[1] = contr;
        out[2] = align;
    }
}

// ================= launch =================
extern "C" void kernel_launch(void* const* d_in, const int* in_sizes, int n_in,
                              void* d_out, int out_size) {
    const float* feature = (const float*)d_in[0];
    const float* text    = (const float*)d_in[1];
    const float* centers = (const float*)d_in[2];
    const int*   positn  = (const int*)d_in[3];
    const int*   cross   = (const int*)d_in[4];
    const int*   vid     = (const int*)d_in[5];
    float* out = (float*)d_out;

    cudaFuncSetAttribute(k_neg, cudaFuncAttributeMaxDynamicSharedMemorySize, NEG_SMEM);

    k_init<<<128, 256>>>();
    k_scatter<<<6, 256>>>(cross, positn);
    k_prep<<<PP*BB, 128>>>(feature, text);
    k_neg<<<dim3(NN/128, PP), 256, NEG_SMEM>>>(feature, centers);
    k_pos<<<PP*BB, 128>>>(feature, centers, cross);
    k_align<<<dim3(16, PP), 256>>>();
    k_final<<<6, 256>>>(cross, vid, out);
}

// round 7
// speedup vs baseline: 2.4783x; 1.0370x over previous
#include <cuda_runtime.h>
#include <cstdint>
#include <math.h>

#define PP 4
#define BB 128
#define DD 512
#define NN 32768
#define KK 10
#define TEMP_INV 2.0f
#define SCALEC 10.0f
#define KL_WEIGHT (59.0f/120.0f)

// ================= scratch (16B-aligned: we float4-cast these) =================
__device__ __align__(16) float g_img[PP*BB*DD];
__device__ __align__(16) float g_txt[PP*BB*DD];
__device__ __align__(16) float g_fn2[PP*BB];
__device__ __align__(16) float g_negmask[NN];
__device__ __align__(16) float g_negsum[PP*BB];
__device__ __align__(16) float g_lp[PP];
__device__ __align__(16) float g_klp[PP];
__device__ int g_done;

// ================= helpers =================
__device__ __forceinline__ void cp16(uint32_t dst, const void* src) {
    asm volatile("cp.async.cg.shared.global [%0], [%1], 16;" :: "r"(dst), "l"(src));
}
#define CP_COMMIT() asm volatile("cp.async.commit_group;" ::: "memory")
#define CP_WAIT1()  asm volatile("cp.async.wait_group 1;" ::: "memory")

__device__ __forceinline__ uint32_t smem_u32(const void* p) {
    uint32_t a;
    asm("{ .reg .u64 t; cvta.to.shared.u64 t, %1; cvt.u32.u64 %0, t; }" : "=r"(a) : "l"(p));
    return a;
}

__device__ __forceinline__ void mma_tf32(float* d, const uint32_t* a, const uint32_t* b) {
    asm volatile(
        "mma.sync.aligned.m16n8k8.row.col.f32.tf32.tf32.f32 "
        "{%0,%1,%2,%3}, {%4,%5,%6,%7}, {%8,%9}, {%0,%1,%2,%3};"
        : "+f"(d[0]), "+f"(d[1]), "+f"(d[2]), "+f"(d[3])
        : "r"(a[0]), "r"(a[1]), "r"(a[2]), "r"(a[3]), "r"(b[0]), "r"(b[1]));
}

// ================= kernel A: housekeeping + normalize =================
// block 0: init mask/accumulators then scatter (single block => ordered).
// blocks 1..512: normalize feature/text row pb = bid-1, compute fn2.
__global__ void __launch_bounds__(128) k_pre(const float* __restrict__ feature,
                                             const float* __restrict__ text,
                                             const int* __restrict__ cross,
                                             const int* __restrict__ pos) {
    int tid = threadIdx.x;
    if (blockIdx.x == 0) {
        for (int i = tid; i < NN; i += 128) g_negmask[i] = 1.0f;
        for (int i = tid; i < PP*BB; i += 128) g_negsum[i] = 0.0f;
        if (tid < PP) { g_lp[tid] = 0.0f; g_klp[tid] = 0.0f; }
        if (tid == 0) g_done = 0;
        __syncthreads();
        for (int i = tid; i < BB*KK; i += 128) g_negmask[cross[i]] = 0.0f;
        for (int i = tid; i < BB; i += 128) g_negmask[pos[i]] = 0.0f;
        return;
    }
    __shared__ float s4[4];
    int pb = blockIdx.x - 1;
    int p = pb >> 7, b = pb & 127;

    float4 f = ((const float4*)(feature + (size_t)pb * DD))[tid];
    float ss = f.x*f.x + f.y*f.y + f.z*f.z + f.w*f.w;
    #pragma unroll
    for (int o = 16; o; o >>= 1) ss += __shfl_xor_sync(~0u, ss, o);
    if ((tid & 31) == 0) s4[tid >> 5] = ss;
    __syncthreads();
    ss = s4[0] + s4[1] + s4[2] + s4[3];
    if (tid == 0) g_fn2[pb] = ss;
    float inv = 1.0f / fmaxf(sqrtf(ss), 1e-12f);
    ((float4*)(g_img + (size_t)pb * DD))[tid] =
        make_float4(f.x*inv, f.y*inv, f.z*inv, f.w*inv);
    __syncthreads();

    float4 t = ((const float4*)(text + ((size_t)b * PP + p) * DD))[tid];
    float ts = t.x*t.x + t.y*t.y + t.z*t.z + t.w*t.w;
    #pragma unroll
    for (int o = 16; o; o >>= 1) ts += __shfl_xor_sync(~0u, ts, o);
    if ((tid & 31) == 0) s4[tid >> 5] = ts;
    __syncthreads();
    ts = s4[0] + s4[1] + s4[2] + s4[3];
    float tinv = 1.0f / fmaxf(sqrtf(ts), 1e-12f);
    ((float4*)(g_txt + (size_t)pb * DD))[tid] =
        make_float4(t.x*tinv, t.y*tinv, t.z*tinv, t.w*tinv);
}

// ================= neg term: tf32 mma.sync GEMM =================
// Block (n0 = bx*128, p = by): D[128 b][128 n] = feature[p] . centers[p, n0:+128]^T
// 8 warps, warp tile 64x32 via m16n8k8. K=512 in 16 chunks of 32.
// 3-stage cp.async, ONE __syncthreads per chunk.
#define KC 32
#define PITCH 36                             // (4*row + k) mod 32 distinct -> conflict-free
#define TILE_BYTES (128 * PITCH * 4)         // 18432
#define STAGE_BYTES (2 * TILE_BYTES)         // 36864 (A + B)
#define STAGES 3
#define NEG_SMEM (STAGES * STAGE_BYTES)      // 110592

__device__ __forceinline__ void load_chunk(const float* __restrict__ A,
                                           const float* __restrict__ B,
                                           uint32_t base, int c, int stage, int tid) {
    int k0 = c * KC;
    uint32_t sA = base + (uint32_t)stage * STAGE_BYTES;
    uint32_t sB = sA + TILE_BYTES;
    #pragma unroll
    for (int i = 0; i < 8; i++) {
        int q = i * 256 + tid;
        int row = (q >> 3) & 127;
        int g = q & 7;
        uint32_t off = (uint32_t)(row * 144 + g * 16);
        if (q < 1024) cp16(sA + off, A + (size_t)row * DD + k0 + g * 4);
        else          cp16(sB + off, B + (size_t)row * DD + k0 + g * 4);
    }
    CP_COMMIT();
}

__global__ void __launch_bounds__(256, 2)
k_neg(const float* __restrict__ feature, const float* __restrict__ centers) {
    extern __shared__ __align__(16) char dsm[];
    __shared__ float s_cn2[128];
    __shared__ float s_fn2[128];
    __shared__ float s_mask[128];
    __shared__ float s_bsum[128];

    uint32_t base = smem_u32(dsm);
    int tid = threadIdx.x;
    int wid = tid >> 5, lane = tid & 31;
    int row4 = lane >> 2, col4 = lane & 3;
    int warp_m = wid >> 2, warp_n = wid & 3;
    int mbase = warp_m * 64, nbase = warp_n * 32;
    int p = blockIdx.y;
    int n0 = blockIdx.x * 128;

    if (tid < 128) {
        s_mask[tid] = g_negmask[n0 + tid];
        s_fn2[tid] = g_fn2[p * BB + tid];
        s_bsum[tid] = 0.0f;
    }

    const float* A = feature + (size_t)p * BB * DD;
    const float* B = centers + ((size_t)p * NN + n0) * DD;

    float acc[4][4][4];
    #pragma unroll
    for (int i = 0; i < 4; i++)
        #pragma unroll
        for (int j = 0; j < 4; j++)
            #pragma unroll
            for (int r = 0; r < 4; r++) acc[i][j][r] = 0.0f;
    float cn2acc = 0.0f;

    load_chunk(A, B, base, 0, 0, tid);
    load_chunk(A, B, base, 1, 1, tid);

    int st = 0, s2 = 2;
    for (int c = 0; c < 16; c++) {
        CP_WAIT1();                 // my chunk-c copies landed
        __syncthreads();            // everyone's landed; stage s2 fully drained (read at c-1)
        if (c + 2 < 16) load_chunk(A, B, base, c + 2, s2, tid);
        else            CP_COMMIT();    // keep group accounting uniform

        const float* sA = (const float*)(dsm + (size_t)st * STAGE_BYTES);
        const float* sB = (const float*)(dsm + (size_t)st * STAGE_BYTES + TILE_BYTES);

        if (tid < 128) {            // cn2 partial from B tile
            const float4* r4 = (const float4*)(sB + tid * PITCH);
            #pragma unroll
            for (int g = 0; g < 8; g++) {
                float4 v = r4[g];
                cn2acc += v.x*v.x + v.y*v.y + v.z*v.z + v.w*v.w;
            }
        }

        #pragma unroll
        for (int kk = 0; kk < 4; kk++) {
            int kf = kk * 8;
            uint32_t afr[4][4];
            #pragma unroll
            for (int i = 0; i < 4; i++) {
                const float* Ar = sA + (mbase + i * 16 + row4) * PITCH + kf + col4;
                afr[i][0] = __float_as_uint(Ar[0]);
                afr[i][1] = __float_as_uint(Ar[8 * PITCH]);
                afr[i][2] = __float_as_uint(Ar[4]);
                afr[i][3] = __float_as_uint(Ar[8 * PITCH + 4]);
            }
            uint32_t bfr[4][2];
            #pragma unroll
            for (int j = 0; j < 4; j++) {
                const float* Br = sB + (nbase + j * 8 + row4) * PITCH + kf + col4;
                bfr[j][0] = __float_as_uint(Br[0]);
                bfr[j][1] = __float_as_uint(Br[4]);
            }
            #pragma unroll
            for (int i = 0; i < 4; i++)
                #pragma unroll
                for (int j = 0; j < 4; j++)
                    mma_tf32(acc[i][j], afr[i], bfr[j]);
        }
        st = (st + 1 == STAGES) ? 0 : st + 1;
        s2 = (s2 + 1 == STAGES) ? 0 : s2 + 1;
    }

    if (tid < 128) s_cn2[tid] = cn2acc;
    __syncthreads();

    #pragma unroll
    for (int i = 0; i < 4; i++) {
        #pragma unroll
        for (int half = 0; half < 2; half++) {
            int b = mbase + i * 16 + row4 + half * 8;
            float fn2v = s_fn2[b];
            float s = 0.0f;
            #pragma unroll
            for (int j = 0; j < 4; j++) {
                #pragma unroll
                for (int q = 0; q < 2; q++) {
                    int n = nbase + j * 8 + col4 * 2 + q;
                    float v = acc[i][j][half * 2 + q];
                    float pd2 = fn2v + s_cn2[n] - 2.0f * v;
                    float dist = sqrtf(fmaxf(pd2, 1e-12f));
                    s += __expf(-SCALEC * dist) * s_mask[n];
                }
            }
            atomicAdd(&s_bsum[b], s);
        }
    }
    __syncthreads();
    if (tid < 128) atomicAdd(&g_negsum[p * BB + tid], s_bsum[tid]);
}

// ================= tail: pos + align + final (one launch) =================
// blocks 0..511: positive term for pb=bid. blocks 512..575: align tile.
// Last finished block computes the scalar outputs + vid gather.
// NOTE: every __shared__ array that is float4-cast is __align__(16) — smem
// allocations from the pos branch precede the align branch's in the layout,
// and an unaligned base here is what faulted R5/R6.
__global__ void __launch_bounds__(256) k_tail(const float* __restrict__ feature,
                                              const float* __restrict__ centers,
                                              const int* __restrict__ cross,
                                              const int* __restrict__ vid,
                                              float* __restrict__ out) {
    int tid = threadIdx.x;
    int bid = blockIdx.x;

    if (bid < 512) {
        // -------- positive term for pb = bid --------
        __shared__ __align__(16) float s_f[DD];
        __shared__ float s_e[KK];
        int pb = bid; int p = pb >> 7, b = pb & 127;
        if (tid < 128) ((float4*)s_f)[tid] = ((const float4*)(feature + (size_t)pb * DD))[tid];
        __syncthreads();
        int w = tid >> 5, lane = tid & 31;
        float fn2 = g_fn2[pb];
        for (int k = w; k < KK; k += 8) {
            int n = cross[b * KK + k];
            const float4* c4 = (const float4*)(centers + ((size_t)p * NN + n) * DD);
            float dot = 0.0f, cn2 = 0.0f;
            for (int i = lane; i < DD/4; i += 32) {
                float4 c = c4[i];
                float4 f = ((const float4*)s_f)[i];
                dot += f.x*c.x + f.y*c.y + f.z*c.z + f.w*c.w;
                cn2 += c.x*c.x + c.y*c.y + c.z*c.z + c.w*c.w;
            }
            #pragma unroll
            for (int o = 16; o; o >>= 1) {
                dot += __shfl_xor_sync(~0u, dot, o);
                cn2 += __shfl_xor_sync(~0u, cn2, o);
            }
            if (lane == 0) {
                float dist = sqrtf(fmaxf(fn2 + cn2 - 2.0f * dot, 1e-12f));
                s_e[k] = expf(-SCALEC * dist);
            }
        }
        __syncthreads();
        if (tid == 0) {
            float se = 0.0f;
            for (int k = 0; k < KK; k++) se += s_e[k];
            atomicAdd(&g_lp[p], logf(g_negsum[pb]) - logf(se));
        }
    } else {
        // -------- align tile: colm/valid provably all-true (diag cos/TEMP = 2 > 0.7) --------
        __shared__ __align__(16) float rows[8][512];
        __shared__ __align__(16) float chunk[128][36];
        __shared__ __align__(16) float sim[2][8][128];
        int ab = bid - 512;
        int p = ab >> 4;
        int r0 = (ab & 15) * 8;
        int c = tid & 127, rh = tid >> 7;

        for (int src = 0; src < 2; src++) {
            const float* X = (src ? g_txt : g_img) + (size_t)p * BB * DD;
            __syncthreads();
            for (int i = tid; i < 8 * 128; i += 256) {
                int r = i >> 7, g = i & 127;
                ((float4*)rows[r])[g] = ((const float4*)(X + (size_t)(r0 + r) * DD))[g];
            }
            float acc[4] = {0.f, 0.f, 0.f, 0.f};
            for (int d0 = 0; d0 < 512; d0 += 32) {
                __syncthreads();
                for (int i = tid; i < 1024; i += 256) {
                    int r = i >> 3, g = i & 7;
                    float4 v = ((const float4*)(X + (size_t)r * DD + d0))[g];
                    chunk[r][g*4+0] = v.x; chunk[r][g*4+1] = v.y;
                    chunk[r][g*4+2] = v.z; chunk[r][g*4+3] = v.w;
                }
                __syncthreads();
                #pragma unroll
                for (int dg = 0; dg < 8; dg++) {
                    float4 cv = *(const float4*)&chunk[c][dg * 4];
                    #pragma unroll
                    for (int i = 0; i < 4; i++) {
                        float4 rv = *(const float4*)&rows[rh * 4 + i][d0 + dg * 4];
                        acc[i] += rv.x*cv.x + rv.y*cv.y + rv.z*cv.z + rv.w*cv.w;
                    }
                }
            }
            #pragma unroll
            for (int i = 0; i < 4; i++) sim[src][rh * 4 + i][c] = acc[i] * TEMP_INV;
        }
        __syncthreads();

        int w = tid >> 5, lane = tid & 31;
        float li[4], lt[4];
        #pragma unroll
        for (int j = 0; j < 4; j++) {
            li[j] = sim[0][w][lane + 32 * j];
            lt[j] = sim[1][w][lane + 32 * j];
        }
        float mi = fmaxf(fmaxf(li[0], li[1]), fmaxf(li[2], li[3]));
        float mt = fmaxf(fmaxf(lt[0], lt[1]), fmaxf(lt[2], lt[3]));
        #pragma unroll
        for (int o = 16; o; o >>= 1) {
            mi = fmaxf(mi, __shfl_xor_sync(~0u, mi, o));
            mt = fmaxf(mt, __shfl_xor_sync(~0u, mt, o));
        }
        float si = 0.f, stt = 0.f;
        #pragma unroll
        for (int j = 0; j < 4; j++) { si += expf(li[j] - mi); stt += expf(lt[j] - mt); }
        #pragma unroll
        for (int o = 16; o; o >>= 1) {
            si += __shfl_xor_sync(~0u, si, o);
            stt += __shfl_xor_sync(~0u, stt, o);
        }
        float Li = mi + logf(si), Lt = mt + logf(stt);
        float kl = 0.f;
        #pragma unroll
        for (int j = 0; j < 4; j++) {
            float lpi = li[j] - Li, lpt = lt[j] - Lt;
            kl += expf(lpt) * (lpt - lpi) + expf(lpi) * (lpi - lpt);
        }
        #pragma unroll
        for (int o = 16; o; o >>= 1) kl += __shfl_xor_sync(~0u, kl, o);
        if (lane == 0) atomicAdd(&g_klp[p], kl);
    }

    // -------- last-block-done: finalize --------
    __shared__ int s_last;
    __syncthreads();
    if (tid == 0) {
        __threadfence();
        s_last = (atomicAdd(&g_done, 1) == 575);
    }
    __syncthreads();
    if (s_last) {
        __threadfence();
        for (int i = tid; i < BB*KK; i += 256) out[3 + i] = (float)vid[__ldcg(&cross[i])];
        if (tid == 0) {
            float contr = 0.0f;
            for (int p = 0; p < PP; p++) {
                float lp = __ldcg(&g_lp[p]) / (float)BB;
                if (isnan(lp)) lp = 0.0f;
                contr += lp;
            }
            contr /= (float)PP;
            float align = 0.0f;
            for (int p = 0; p < PP; p++) align += 0.5f * __ldcg(&g_klp[p]) / (float)BB;
            out[0] = contr + KL_WEIGHT * align;
            out[1] = contr;
            out[2] = align;
        }
    }
}

// ================= launch =================
extern "C" void kernel_launch(void* const* d_in, const int* in_sizes, int n_in,
                              void* d_out, int out_size) {
    const float* feature = (const float*)d_in[0];
    const float* text    = (const float*)d_in[1];
    const float* centers = (const float*)d_in[2];
    const int*   positn  = (const int*)d_in[3];
    const int*   cross   = (const int*)d_in[4];
    const int*   vid     = (const int*)d_in[5];
    float* out = (float*)d_out;

    cudaFuncSetAttribute(k_neg, cudaFuncAttributeMaxDynamicSharedMemorySize, NEG_SMEM);

    k_pre<<<513, 128>>>(feature, text, cross, positn);
    k_neg<<<dim3(NN/128, PP), 256, NEG_SMEM>>>(feature, centers);
    k_tail<<<576, 256>>>(feature, centers, cross, vid, out);
}